// round 11
// baseline (speedup 1.0000x reference)
#include <cuda_runtime.h>
#include <stdint.h>

#define BATCH 128
#define NQ    2000
#define NC    3
#define QC    6000
#define NV4   1500          // QC/4
#define TOPK  100
#define NP    20
#define NPQ   (NP * 2 / 4)  // 10 float4 per selection
#define NT    512
#define NW    (NT / 32)     // 16 warps
#define NJ4   3             // ceil(NV4/NT)
#define NKEY  (NJ4 * 4)     // 12 keys/thread
#define NBINS 4096
#define BPT   8             // NBINS/NT
#define CAND_CAP 1024
#define PAIR_CAP (NT / 2)   // 256 candidates ranked in the cooperative pass

// Output layout (float32, reference tuple order, flattened):
#define OFF_BOXES  0
#define OFF_SCORES 51200
#define OFF_LABELS 64000
#define OFF_PTS    76800
#define OFF_MASK   588800

__device__ __forceinline__ unsigned int mono_key(float x) {
    unsigned int u = __float_as_uint(x);
    return (u & 0x80000000u) ? ~u : (u | 0x80000000u);
}

__global__ __launch_bounds__(NT, 1)
void maptr_post_kernel(const float* __restrict__ cls,
                       const float* __restrict__ bbox,
                       const float* __restrict__ pts,
                       float* __restrict__ out)
{
    __shared__ unsigned long long cand[CAND_CAP];     // 8 KB
    __shared__ unsigned int       warp_cnt[NW];
    // staged decode results, indexed by rank
    __shared__ float4             sbox[TOPK];
    __shared__ float              ssc[TOPK];
    __shared__ float              slab[TOPK];
    __shared__ float              smsk[TOPK];
    __shared__ int                sbi[TOPK];
    // fallback-only shared
    __shared__ unsigned int       hist[NBINS];        // 16 KB
    __shared__ unsigned int       warp_tot[NW];
    __shared__ int                sh_bcut;
    __shared__ int                n_cand;

    const int b    = blockIdx.x;
    const int t    = threadIdx.x;
    const int wid  = t >> 5;
    const int lane = t & 31;
    const unsigned int lt_mask = (1u << lane) - 1u;

    // ---- issue global loads first ----
    const float4* logit4 = (const float4*)(cls + (size_t)(5 * BATCH + b) * QC);
    float4 w[NJ4];
    bool   wv[NJ4];
#pragma unroll
    for (int v = 0; v < NJ4; v++) {
        const int idx4 = t + v * NT;
        wv[v] = (idx4 < NV4);
        w[v] = wv[v] ? logit4[idx4] : make_float4(0.f, 0.f, 0.f, 0.f);
    }

    // ---- keys in registers ----
    unsigned int key[NKEY];
#pragma unroll
    for (int v = 0; v < NJ4; v++) {
        key[v * 4 + 0] = wv[v] ? mono_key(w[v].x) : 0u;
        key[v * 4 + 1] = wv[v] ? mono_key(w[v].y) : 0u;
        key[v * 4 + 2] = wv[v] ? mono_key(w[v].z) : 0u;
        key[v * 4 + 3] = wv[v] ? mono_key(w[v].w) : 0u;
    }

    // ---- speculative ballots at fixed threshold (logit >= 1.9), no atomics ----
    const unsigned int SPEC_CUT = __float_as_uint(1.9f) | 0x80000000u;
    unsigned int msk[NKEY];
    unsigned int mycnt = 0u;
#pragma unroll
    for (int j = 0; j < NKEY; j++) {
        msk[j] = __ballot_sync(0xFFFFFFFFu, key[j] >= SPEC_CUT);
        mycnt += __popc(msk[j]);
    }
    if (lane == 0) warp_cnt[wid] = mycnt;
    __syncthreads();

    int base = 0, C = 0;
#pragma unroll
    for (int i = 0; i < NW; i++) {
        const int c = (int)warp_cnt[i];
        base += (i < wid) ? c : 0;
        C += c;
    }

    if (C >= TOPK && C <= CAND_CAP) {
        // ---- deterministic atomic-free collect ----
        int off = base;
#pragma unroll
        for (int v = 0; v < NJ4; v++) {
            const int idx4 = t + v * NT;
#pragma unroll
            for (int c4 = 0; c4 < 4; c4++) {
                const int j = v * 4 + c4;
                if (key[j] >= SPEC_CUT) {
                    const int p = off + __popc(msk[j] & lt_mask);
                    cand[p] = ((unsigned long long)key[j] << 32) |
                              (unsigned int)(0xFFFFFFFFu - (unsigned int)(idx4 * 4 + c4));
                }
                off += __popc(msk[j]);
            }
        }
        __syncthreads();
    } else {
        // ---- fallback: exact histogram cutoff (rare; correctness for any input) ----
#pragma unroll
        for (int i = 0; i < NBINS / NT; i++) hist[t + i * NT] = 0u;
        if (t == 0) n_cand = 0;
        __syncthreads();

#pragma unroll
        for (int v = 0; v < NJ4; v++) {
            if (wv[v]) {
                atomicAdd(&hist[key[v * 4 + 0] >> 20], 1u);
                atomicAdd(&hist[key[v * 4 + 1] >> 20], 1u);
                atomicAdd(&hist[key[v * 4 + 2] >> 20], 1u);
                atomicAdd(&hist[key[v * 4 + 3] >> 20], 1u);
            }
        }
        __syncthreads();

        const int bin_hi = NBINS - 1 - BPT * t;
        unsigned int ssum = 0u;
#pragma unroll
        for (int k = 0; k < BPT; k++) ssum += hist[bin_hi - k];
        unsigned int inc = ssum;
#pragma unroll
        for (int off2 = 1; off2 < 32; off2 <<= 1) {
            unsigned int v = __shfl_up_sync(0xFFFFFFFFu, inc, off2);
            if (lane >= off2) inc += v;
        }
        if (lane == 31) warp_tot[wid] = inc;
        __syncthreads();
        unsigned int woff = 0u;
        for (int i = 0; i < wid; i++) woff += warp_tot[i];
        const unsigned int excl = woff + inc - ssum;
        if (excl < TOPK && excl + ssum >= TOPK) {
            unsigned int acc = excl;
            int bc = bin_hi;
#pragma unroll
            for (int k = 0; k < BPT; k++) {
                acc += hist[bin_hi - k];
                if (acc >= TOPK) { bc = bin_hi - k; break; }
            }
            sh_bcut = bc;
        }
        __syncthreads();
        const unsigned int keycut = ((unsigned int)sh_bcut) << 20;

#pragma unroll
        for (int v = 0; v < NJ4; v++) {
            const int idx4 = t + v * NT;
#pragma unroll
            for (int c4 = 0; c4 < 4; c4++) {
                const unsigned int k = key[v * 4 + c4];
                const bool pred = (k >= keycut) && (k != 0u);
                const unsigned int mask = __ballot_sync(0xFFFFFFFFu, pred);
                if (mask) {
                    int bs;
                    if (lane == 0) bs = atomicAdd(&n_cand, __popc(mask));
                    bs = __shfl_sync(0xFFFFFFFFu, bs, 0);
                    if (pred) {
                        int p = bs + __popc(mask & lt_mask);
                        if (p < CAND_CAP)
                            cand[p] = ((unsigned long long)k << 32) |
                                      (unsigned int)(0xFFFFFFFFu - (unsigned int)(idx4 * 4 + c4));
                    }
                }
            }
        }
        __syncthreads();
        C = (n_cand < CAND_CAP) ? n_cand : CAND_CAP;
    }

    const float* bbp = bbox + (size_t)(5 * BATCH + b) * NQ * 4;

    // ---- cooperative pairwise rank: 2 threads per candidate ----
    {
        const int cid  = t >> 1;
        const int half = t & 1;
        const int mid  = C >> 1;
        const int lo   = half ? mid : 0;
        const int hi   = half ? C   : mid;

        const unsigned long long me = (cid < C) ? cand[cid] : 0ull;

        int partial = 0;
        int jj = lo;
        for (; jj + 4 <= hi; jj += 4) {
            partial += (cand[jj]     > me);
            partial += (cand[jj + 1] > me);
            partial += (cand[jj + 2] > me);
            partial += (cand[jj + 3] > me);
        }
        for (; jj < hi; jj++) partial += (cand[jj] > me);

        const int rank = partial + __shfl_xor_sync(0xFFFFFFFFu, partial, 1);

        if (half == 0 && cid < C && cid < PAIR_CAP && rank < TOPK) {
            const int g   = (int)(0xFFFFFFFFu - (unsigned int)me);
            const int bi  = g / NC;
            const int lab = g - bi * NC;

            float4 bv = *(const float4*)(bbp + (size_t)bi * 4);

            unsigned int mono = (unsigned int)(me >> 32);
            unsigned int u = (mono & 0x80000000u) ? (mono ^ 0x80000000u) : ~mono;
            float f = __uint_as_float(u);
            float score = 1.0f / (1.0f + __expf(-f));

            float x1 = (bv.x - 0.5f * bv.z) * 30.0f - 15.0f;
            float y1 = (bv.y - 0.5f * bv.w) * 60.0f - 30.0f;
            float x2 = (bv.x + 0.5f * bv.z) * 30.0f - 15.0f;
            float y2 = (bv.y + 0.5f * bv.w) * 60.0f - 30.0f;

            const bool mk =
                (x1 >= -20.0f) && (y1 >= -35.0f) && (x2 >= -20.0f) && (y2 >= -35.0f) &&
                (x1 <=  20.0f) && (y1 <=  35.0f) && (x2 <=  20.0f) && (y2 <=  35.0f);
            const float sel = mk ? 1.0f : 0.0f;

            sbox[rank] = make_float4(x1 * sel, y1 * sel, x2 * sel, y2 * sel);
            ssc[rank]  = score * sel;
            slab[rank] = mk ? (float)lab : -1.0f;
            smsk[rank] = sel;
            sbi[rank]  = mk ? bi : -1;
        }
    }

    // ---- tail for C > PAIR_CAP (rare; exactness for arbitrary inputs) ----
    for (int i = PAIR_CAP + t; i < C; i += NT) {
        const unsigned long long me = cand[i];
        int rank = 0;
        for (int jj = 0; jj < C; jj++) rank += (cand[jj] > me);
        if (rank < TOPK) {
            const int g   = (int)(0xFFFFFFFFu - (unsigned int)me);
            const int bi  = g / NC;
            const int lab = g - bi * NC;
            float4 bv = *(const float4*)(bbp + (size_t)bi * 4);
            unsigned int mono = (unsigned int)(me >> 32);
            unsigned int u = (mono & 0x80000000u) ? (mono ^ 0x80000000u) : ~mono;
            float score = 1.0f / (1.0f + __expf(-__uint_as_float(u)));
            float x1 = (bv.x - 0.5f * bv.z) * 30.0f - 15.0f;
            float y1 = (bv.y - 0.5f * bv.w) * 60.0f - 30.0f;
            float x2 = (bv.x + 0.5f * bv.z) * 30.0f - 15.0f;
            float y2 = (bv.y + 0.5f * bv.w) * 60.0f - 30.0f;
            const bool mk =
                (x1 >= -20.0f) && (y1 >= -35.0f) && (x2 >= -20.0f) && (y2 >= -35.0f) &&
                (x1 <=  20.0f) && (y1 <=  35.0f) && (x2 <=  20.0f) && (y2 <=  35.0f);
            const float sel = mk ? 1.0f : 0.0f;
            sbox[rank] = make_float4(x1 * sel, y1 * sel, x2 * sel, y2 * sel);
            ssc[rank]  = score * sel;
            slab[rank] = mk ? (float)lab : -1.0f;
            smsk[rank] = sel;
            sbi[rank]  = mk ? bi : -1;
        }
    }
    __syncthreads();

    // ---- coalesced output: boxes/scores/labels/mask ----
    if (t < TOPK) {
        ((float4*)(out + OFF_BOXES))[b * TOPK + t] = sbox[t];
        out[OFF_SCORES + b * TOPK + t] = ssc[t];
        out[OFF_LABELS + b * TOPK + t] = slab[t];
        out[OFF_MASK   + b * TOPK + t] = smsk[t];
    }

    // ---- cooperative pts gather: 1000 float4 tasks, coalesced writes ----
    const float4* pp4 = (const float4*)(pts + (size_t)(5 * BATCH + b) * NQ * NP * 2);
    float4*       op4 = (float4*)(out + OFF_PTS + (size_t)b * TOPK * NP * 2);
#pragma unroll
    for (int i = t; i < TOPK * NPQ; i += NT) {
        const int m  = i / NPQ;
        const int q  = i - m * NPQ;
        const int bi = sbi[m];
        float4 r = make_float4(0.f, 0.f, 0.f, 0.f);
        if (bi >= 0) {
            r = pp4[(size_t)bi * NPQ + q];
            r.x = r.x * 30.0f - 15.0f;
            r.y = r.y * 60.0f - 30.0f;
            r.z = r.z * 30.0f - 15.0f;
            r.w = r.w * 60.0f - 30.0f;
        }
        op4[i] = r;
    }
}

extern "C" void kernel_launch(void* const* d_in, const int* in_sizes, int n_in,
                              void* d_out, int out_size)
{
    const float* cls = nullptr;
    const float* bb  = nullptr;
    const float* pt  = nullptr;
    for (int i = 0; i < n_in; i++) {
        if      (in_sizes[i] == 4608000)  cls = (const float*)d_in[i];
        else if (in_sizes[i] == 6144000)  bb  = (const float*)d_in[i];
        else if (in_sizes[i] == 61440000) pt  = (const float*)d_in[i];
    }
    if (!cls && n_in > 0) cls = (const float*)d_in[0];
    if (!bb  && n_in > 1) bb  = (const float*)d_in[1];
    if (!pt  && n_in > 2) pt  = (const float*)d_in[2];

    maptr_post_kernel<<<BATCH, NT>>>(cls, bb, pt, (float*)d_out);
    (void)out_size;
}